// round 1
// baseline (speedup 1.0000x reference)
#include <cuda_runtime.h>
#include <cstdint>

// LengthRegulator: expand hidden_phonems [B,L,D] by per-phoneme durations [B,L]
// into out [B, max_T, D], zero-padded per batch beyond totals[b].
//
// Strategy:
//   K1: per-batch inclusive scan of durations (1 block/batch, 512 thr),
//       scatter phoneme index into idx_map[b][start..start+d), write totals[b].
//   K2: bandwidth kernel — 64 threads per output frame, float4 gather/store.

#define B_CONST 32
#define L_CONST 512
#define D_CONST 256
#define MAXT_CAP 3584   // L * (MAX_DUR-1) upper bound on any batch total

// scratch (no cudaMalloc allowed)
__device__ int g_idx_map[B_CONST * MAXT_CAP];
__device__ int g_totals[B_CONST];

__global__ void lr_scan_scatter(const int* __restrict__ durations) {
    const int b = blockIdx.x;
    const int l = threadIdx.x;            // 512 threads == L
    const int d = durations[b * L_CONST + l];

    // warp-level inclusive scan
    int v = d;
    #pragma unroll
    for (int o = 1; o < 32; o <<= 1) {
        int n = __shfl_up_sync(0xffffffffu, v, o);
        if ((l & 31) >= o) v += n;
    }

    __shared__ int wsum[16];
    if ((l & 31) == 31) wsum[l >> 5] = v;
    __syncthreads();

    if (l < 16) {
        int w = wsum[l];
        #pragma unroll
        for (int o = 1; o < 16; o <<= 1) {
            int n = __shfl_up_sync(0x0000ffffu, w, o);
            if (l >= o) w += n;
        }
        wsum[l] = w;
    }
    __syncthreads();

    const int incl  = v + ((l >= 32) ? wsum[(l >> 5) - 1] : 0);
    const int start = incl - d;

    int* map = g_idx_map + b * MAXT_CAP;
    for (int j = 0; j < d; ++j) map[start + j] = l;

    if (l == L_CONST - 1) g_totals[b] = incl;
}

// 256 threads per block: 4 frames/block, 64 threads (float4 lanes) per frame.
__global__ void lr_gather(const float4* __restrict__ hidden4,
                          float4* __restrict__ out4,
                          int max_T) {
    const int b    = blockIdx.y;
    const int t    = blockIdx.x * 4 + (threadIdx.x >> 6);
    const int lane = threadIdx.x & 63;    // D/4 = 64 float4 per frame
    if (t >= max_T) return;

    float4 v = make_float4(0.f, 0.f, 0.f, 0.f);
    if (t < g_totals[b]) {
        const int idx = g_idx_map[b * MAXT_CAP + t];
        v = hidden4[((size_t)b * L_CONST + idx) * (D_CONST / 4) + lane];
    }
    out4[((size_t)b * max_T + t) * (D_CONST / 4) + lane] = v;
}

extern "C" void kernel_launch(void* const* d_in, const int* in_sizes, int n_in,
                              void* d_out, int out_size) {
    const float* hidden    = (const float*)d_in[0];   // [B, L, D] fp32
    const int*   durations = (const int*)d_in[1];     // [B, L] int32
    float*       out       = (float*)d_out;

    const int max_T = out_size / (B_CONST * D_CONST);

    lr_scan_scatter<<<B_CONST, L_CONST>>>(durations);

    dim3 grid((max_T + 3) / 4, B_CONST);
    lr_gather<<<grid, 256>>>((const float4*)hidden, (float4*)out, max_T);
}

// round 2
// speedup vs baseline: 1.1345x; 1.1345x over previous
#include <cuda_runtime.h>
#include <cstdint>

// LengthRegulator: expand hidden_phonems [B,L,D] by durations [B,L] into
// out [B, max_T, D], zero-padded beyond totals[b].
//
// R2: gather kernel processes 4 frames/thread to get MLP=4 on the dependent
// idx->gather chain (R1 showed latency-bound: DRAM 12.6%, issue 28.6%).

#define B_CONST 32
#define L_CONST 512
#define D_CONST 256
#define MAXT_CAP 3584   // L * (MAX_DUR-1) bound on any batch total
#define FRAMES_PER_THREAD 4
#define FRAMES_PER_BLOCK  16  // 256 thr / 64 lanes * 4 frames

// scratch (no cudaMalloc allowed)
__device__ int g_idx_map[B_CONST * MAXT_CAP];
__device__ int g_totals[B_CONST];

__global__ void lr_scan_scatter(const int* __restrict__ durations) {
    const int b = blockIdx.x;
    const int l = threadIdx.x;            // 512 threads == L
    const int d = durations[b * L_CONST + l];

    // warp-level inclusive scan
    int v = d;
    #pragma unroll
    for (int o = 1; o < 32; o <<= 1) {
        int n = __shfl_up_sync(0xffffffffu, v, o);
        if ((l & 31) >= o) v += n;
    }

    __shared__ int wsum[16];
    if ((l & 31) == 31) wsum[l >> 5] = v;
    __syncthreads();

    if (l < 16) {
        int w = wsum[l];
        #pragma unroll
        for (int o = 1; o < 16; o <<= 1) {
            int n = __shfl_up_sync(0x0000ffffu, w, o);
            if (l >= o) w += n;
        }
        wsum[l] = w;
    }
    __syncthreads();

    const int incl  = v + ((l >= 32) ? wsum[(l >> 5) - 1] : 0);
    const int start = incl - d;

    int* map = g_idx_map + b * MAXT_CAP;
    for (int j = 0; j < d; ++j) map[start + j] = l;

    if (l == L_CONST - 1) g_totals[b] = incl;
}

// 256 threads/block, 16 frames/block, 4 frames/thread.
// Thread layout: lane = tid&63 covers D (float4), fgrp = tid>>6;
// thread handles frames t0+4j, j=0..3 with t0 = blk*16 + fgrp.
__global__ void lr_gather(const float4* __restrict__ hidden4,
                          float4* __restrict__ out4,
                          int max_T) {
    const int b    = blockIdx.y;
    const int fgrp = threadIdx.x >> 6;
    const int lane = threadIdx.x & 63;
    const int t0   = blockIdx.x * FRAMES_PER_BLOCK + fgrp;
    const int total = g_totals[b];

    const int* __restrict__ map = g_idx_map + b * MAXT_CAP;

    // Phase 1: 4 independent idx loads (L1/L2-hit, warp-broadcast)
    int  idx[FRAMES_PER_THREAD];
    bool live[FRAMES_PER_THREAD];
    #pragma unroll
    for (int j = 0; j < FRAMES_PER_THREAD; ++j) {
        const int t = t0 + 4 * j;
        live[j] = (t < total);
        idx[j]  = live[j] ? map[t] : 0;   // 0 is a safe in-bounds index
    }

    // Phase 2: 4 independent gathers in flight (MLP=4)
    float4 v[FRAMES_PER_THREAD];
    #pragma unroll
    for (int j = 0; j < FRAMES_PER_THREAD; ++j) {
        v[j] = hidden4[((size_t)b * L_CONST + idx[j]) * (D_CONST / 4) + lane];
    }

    // Phase 3: zero padding frames, 4 coalesced stores
    #pragma unroll
    for (int j = 0; j < FRAMES_PER_THREAD; ++j) {
        if (!live[j]) v[j] = make_float4(0.f, 0.f, 0.f, 0.f);
    }
    #pragma unroll
    for (int j = 0; j < FRAMES_PER_THREAD; ++j) {
        const int t = t0 + 4 * j;
        if (t < max_T)
            out4[((size_t)b * max_T + t) * (D_CONST / 4) + lane] = v[j];
    }
}

extern "C" void kernel_launch(void* const* d_in, const int* in_sizes, int n_in,
                              void* d_out, int out_size) {
    const float* hidden    = (const float*)d_in[0];   // [B, L, D] fp32
    const int*   durations = (const int*)d_in[1];     // [B, L] int32
    float*       out       = (float*)d_out;

    const int max_T = out_size / (B_CONST * D_CONST);

    lr_scan_scatter<<<B_CONST, L_CONST>>>(durations);

    dim3 grid((max_T + FRAMES_PER_BLOCK - 1) / FRAMES_PER_BLOCK, B_CONST);
    lr_gather<<<grid, 256>>>((const float4*)hidden, (float4*)out, max_T);
}